// round 13
// baseline (speedup 1.0000x reference)
#include <cuda_runtime.h>
#include <cuda_fp16.h>
#include <math.h>
#include <stdint.h>

// ---------------- problem constants ----------------
#define M_TOK 32768          // 8 * 4096 tokens
#define SEQ   4096
#define DIM   384
#define NH    6
#define HD    64
#define BH    48             // batch*heads
#define QKVN  1152
#define HID   1536

// ---------------- scratch (static device arrays; no allocation) ----------------
__device__ __half g_ln  [(size_t)M_TOK * DIM];       // LN outputs (GEMM A), fp16
__device__ __half g_qkv [(size_t)M_TOK * QKVN];      // qkv, fp16
__device__ __half g_attn[(size_t)M_TOK * DIM];       // attn out (GEMM A), fp16
__device__ float  g_x1  [(size_t)M_TOK * DIM];
__device__ __half g_mlp [(size_t)M_TOK * HID];       // gelu out (GEMM A), fp16
__device__ float  g_kv  [BH * HD * HD];
__device__ float  g_ksum[BH * HD];
// fp16 weights (converted once per launch), [K][N] layout
__device__ __half g_wq [DIM * QKVN];
__device__ __half g_wp [DIM * DIM];
__device__ __half g_w1 [DIM * HID];
__device__ __half g_w2 [HID * DIM];

// ---------------- convert ALL weight matrices to fp16 in one launch ----------------
#define CVT_TOTAL4 442368
__global__ __launch_bounds__(256) void cvt_all_w_kernel(
    const float* __restrict__ qkv_w, const float* __restrict__ proj_w,
    const float* __restrict__ fc1_w, const float* __restrict__ fc2_w)
{
    const int i = blockIdx.x * 256 + threadIdx.x;
    if (i >= CVT_TOTAL4) return;
    const float* src;
    __half* dst;
    int off;
    if (i < 110592)      { src = qkv_w;  dst = g_wq; off = i; }
    else if (i < 147456) { src = proj_w; dst = g_wp; off = i - 110592; }
    else if (i < 294912) { src = fc1_w;  dst = g_w1; off = i - 147456; }
    else                 { src = fc2_w;  dst = g_w2; off = i - 294912; }
    float4 v = ((const float4*)src)[off];
    __half2* d = (__half2*)(dst + (size_t)off * 4);
    d[0] = __floats2half2_rn(v.x, v.y);
    d[1] = __floats2half2_rn(v.z, v.w);
}

// ---------------- LayerNorm: warp per row, fp16 output ----------------
__global__ __launch_bounds__(256) void ln_kernel(
    const float* __restrict__ x, const float* __restrict__ gma,
    const float* __restrict__ bta, __half* __restrict__ out)
{
    const int warp = threadIdx.x >> 5;
    const int lane = threadIdx.x & 31;
    const int row  = blockIdx.x * 8 + warp;
    const float4* xr = (const float4*)(x + (size_t)row * DIM);
    const float4* g4 = (const float4*)gma;
    const float4* b4 = (const float4*)bta;

    float4 v[3];
    #pragma unroll
    for (int i = 0; i < 3; i++) v[i] = xr[lane + i * 32];

    float s = 0.f, sq = 0.f;
    #pragma unroll
    for (int i = 0; i < 3; i++) {
        s  += v[i].x + v[i].y + v[i].z + v[i].w;
        sq += v[i].x*v[i].x + v[i].y*v[i].y + v[i].z*v[i].z + v[i].w*v[i].w;
    }
    #pragma unroll
    for (int o = 16; o > 0; o >>= 1) {
        s  += __shfl_xor_sync(0xffffffffu, s,  o);
        sq += __shfl_xor_sync(0xffffffffu, sq, o);
    }
    const float mean = s * (1.f / DIM);
    const float inv  = rsqrtf(sq * (1.f / DIM) - mean * mean + 1e-5f);

    #pragma unroll
    for (int i = 0; i < 3; i++) {
        const float4 gg = g4[lane + i * 32];
        const float4 bb = b4[lane + i * 32];
        __half2* d = (__half2*)(out + (size_t)row * DIM + (lane + i * 32) * 4);
        d[0] = __floats2half2_rn((v[i].x - mean) * inv * gg.x + bb.x,
                                 (v[i].y - mean) * inv * gg.y + bb.y);
        d[1] = __floats2half2_rn((v[i].z - mean) * inv * gg.z + bb.z,
                                 (v[i].w - mean) * inv * gg.w + bb.w);
    }
}

// ---------------- fp16 tensor-core GEMM, cp.async 4-stage pipeline ----------------
// 128x128x32 CTA tile, 256 threads = 8 warps (2x4), warp tile 64x32, m16n8k16 fp16
// with fp32 accumulate.
//   MODE 0: qkv  -> phi on cols<768, fp16 out
//   MODE 1: proj -> +res, fp32 out
//   MODE 2: fc1  -> gelu, fp16 out
//   MODE 3: fc2  -> +res, fp32 out

#define BM 128
#define BN 128
#define BK 32
#define STAGES 4
#define AS_STRIDE 40                    // halfs; 80B row stride (conflict-free ldsm)
#define BS_STRIDE 136                   // halfs; 272B row stride (conflict-free ldsm.trans)
#define AS_BUF (BM * AS_STRIDE)
#define BS_BUF (BK * BS_STRIDE)
#define GEMM_SMEM_BYTES (STAGES * (AS_BUF + BS_BUF) * 2)   // 75776

__device__ __forceinline__ void cp16h(__half* dst, const __half* src) {
    uint32_t s = (uint32_t)__cvta_generic_to_shared(dst);
    asm volatile("cp.async.cg.shared.global [%0], [%1], 16;" :: "r"(s), "l"(src));
}

__device__ __forceinline__ void ldsm_x4(uint32_t* r, const __half* p) {
    uint32_t a = (uint32_t)__cvta_generic_to_shared(p);
    asm volatile("ldmatrix.sync.aligned.m8n8.x4.shared.b16 {%0,%1,%2,%3}, [%4];"
        : "=r"(r[0]), "=r"(r[1]), "=r"(r[2]), "=r"(r[3]) : "r"(a));
}

__device__ __forceinline__ void ldsm_x4_t(uint32_t* r, const __half* p) {
    uint32_t a = (uint32_t)__cvta_generic_to_shared(p);
    asm volatile("ldmatrix.sync.aligned.m8n8.x4.trans.shared.b16 {%0,%1,%2,%3}, [%4];"
        : "=r"(r[0]), "=r"(r[1]), "=r"(r[2]), "=r"(r[3]) : "r"(a));
}

__device__ __forceinline__ void mma_f16(float* d, const uint32_t* a, const uint32_t* b) {
    asm volatile(
        "mma.sync.aligned.m16n8k16.row.col.f32.f16.f16.f32 "
        "{%0,%1,%2,%3}, {%4,%5,%6,%7}, {%8,%9}, {%0,%1,%2,%3};"
        : "+f"(d[0]), "+f"(d[1]), "+f"(d[2]), "+f"(d[3])
        : "r"(a[0]), "r"(a[1]), "r"(a[2]), "r"(a[3]), "r"(b[0]), "r"(b[1]));
}

__device__ __forceinline__ float fast_gelu(float v) {
    const float two_u = 1.5957691216057308f * (v + 0.044715f * v * v * v);
    return v * (1.f / (1.f + __expf(-two_u)));
}

template<int MODE>
__global__ __launch_bounds__(256, 2) void gemm_f16(
    const __half* __restrict__ A, const __half* __restrict__ W,
    const float* __restrict__ bias, const float* __restrict__ res,
    void* __restrict__ Cout, int N, int K)
{
    extern __shared__ __align__(16) __half smem_h[];
    __half* As = smem_h;                          // [STAGES][BM][AS_STRIDE]
    __half* Bs = smem_h + STAGES * AS_BUF;        // [STAGES][BK][BS_STRIDE]

    const int tid  = threadIdx.x;
    const int lane = tid & 31;
    const int warp = tid >> 5;
    const int wm = warp >> 2;          // 0..1
    const int wn = warp & 3;           // 0..3
    const int g  = lane >> 2;          // 0..7
    const int tg = lane & 3;           // 0..3

    const int lm_r = ((lane >> 3) & 1) * 8 + (lane & 7);
    const int lm_c = (lane >> 4) * 8;

    const int bm = blockIdx.y * BM;
    const int bn = blockIdx.x * BN;
    const int T  = K / BK;

    auto stage = [&](int t) {
        const int s  = t % STAGES;
        const int kt = t * BK;
        __half* Ad = As + s * AS_BUF;
        __half* Bd = Bs + s * BS_BUF;
        #pragma unroll
        for (int i = 0; i < 2; i++) {
            const int idx = tid + i * 256;
            const int m = idx >> 2, c = (idx & 3) * 8;
            cp16h(&Ad[m * AS_STRIDE + c], A + (size_t)(bm + m) * K + kt + c);
        }
        #pragma unroll
        for (int i = 0; i < 2; i++) {
            const int idx = tid + i * 256;
            const int k = idx >> 4, c = (idx & 15) * 8;
            cp16h(&Bd[k * BS_STRIDE + c], W + (size_t)(kt + k) * N + bn + c);
        }
        asm volatile("cp.async.commit_group;");
    };

    stage(0);
    stage(1);
    stage(2);

    float acc[4][4][4] = {};
    const int m_base = wm * 64;
    const int n_base = wn * 32;

    int buf = 0;
    for (int t = 0; t < T; t++) {
        asm volatile("cp.async.wait_group 2;");
        __syncthreads();

        const __half* Ab = As + buf * AS_BUF;
        const __half* Bb = Bs + buf * BS_BUF;

        #pragma unroll
        for (int ks = 0; ks < 2; ks++) {
            const int k0 = ks * 16;
            uint32_t af[4][4], bf[4][2];
            #pragma unroll
            for (int mt = 0; mt < 4; mt++)
                ldsm_x4(af[mt], Ab + (m_base + mt * 16 + lm_r) * AS_STRIDE + k0 + lm_c);
            #pragma unroll
            for (int np = 0; np < 2; np++) {
                uint32_t r[4];
                ldsm_x4_t(r, Bb + (k0 + lm_r) * BS_STRIDE + n_base + np * 16 + lm_c);
                bf[np * 2    ][0] = r[0]; bf[np * 2    ][1] = r[1];
                bf[np * 2 + 1][0] = r[2]; bf[np * 2 + 1][1] = r[3];
            }
            #pragma unroll
            for (int mt = 0; mt < 4; mt++)
                #pragma unroll
                for (int nt = 0; nt < 4; nt++)
                    mma_f16(acc[mt][nt], af[mt], bf[nt]);
        }

        if (t + 3 < T) stage(t + 3);
        else asm volatile("cp.async.commit_group;");

        buf = (buf + 1 == STAGES) ? 0 : buf + 1;
    }

    // ---------------- epilogue ----------------
    float*  Cf = (float*)Cout;
    __half* Ch = (__half*)Cout;
    #pragma unroll
    for (int mt = 0; mt < 4; mt++) {
        #pragma unroll
        for (int half_i = 0; half_i < 2; half_i++) {
            const int row = bm + m_base + mt * 16 + g + half_i * 8;
            #pragma unroll
            for (int nt = 0; nt < 4; nt++) {
                const int col = bn + n_base + nt * 8 + tg * 2;
                float v0 = acc[mt][nt][half_i * 2 + 0] + bias[col];
                float v1 = acc[mt][nt][half_i * 2 + 1] + bias[col + 1];
                if (MODE == 0) {
                    if (col     < 768) v0 = (v0 > 0.f) ? (v0 + 1.f) : __expf(v0);
                    if (col + 1 < 768) v1 = (v1 > 0.f) ? (v1 + 1.f) : __expf(v1);
                    *(__half2*)(Ch + (size_t)row * N + col) = __floats2half2_rn(v0, v1);
                }
                if (MODE == 1 || MODE == 3) {
                    const float2 r = *(const float2*)(res + (size_t)row * N + col);
                    v0 += r.x; v1 += r.y;
                    *(float2*)(Cf + (size_t)row * N + col) = make_float2(v0, v1);
                }
                if (MODE == 2) {
                    v0 = fast_gelu(v0);
                    v1 = fast_gelu(v1);
                    *(__half2*)(Ch + (size_t)row * N + col) = __floats2half2_rn(v0, v1);
                }
            }
        }
    }
}

// ---------------- zero kv state ----------------
__global__ void zero_kv_kernel()
{
    const int i = blockIdx.x * blockDim.x + threadIdx.x;
    if (i < BH * HD * HD) g_kv[i] = 0.f;
    if (i < BH * HD)      g_ksum[i] = 0.f;
}

// ---------------- kv-state: kv[bh] += K^T V over a 128-row chunk (fp16 in) ----------------
#define KV_CHUNK 128
__global__ __launch_bounds__(256) void kv_kernel()
{
    const int bh = blockIdx.y;
    const int b  = bh / NH, h = bh % NH;
    const int nbase = blockIdx.x * KV_CHUNK;

    __shared__ float ks[64][64];
    __shared__ float vs[64][64];

    const int tid = threadIdx.x;
    const int tx = tid & 15, ty = tid >> 4;
    const int e0 = tx * 4, d0 = ty * 4;

    float acc[4][4] = {};
    float ksacc = 0.f;

    for (int rb = 0; rb < KV_CHUNK; rb += 64) {
        const __half* base = g_qkv + (size_t)(b * SEQ + nbase + rb) * QKVN + h * HD;
        for (int i = tid; i < 1024; i += 256) {
            const int r = i >> 4, c = (i & 15) << 2;
            const __half2* kp = (const __half2*)(base + (size_t)r * QKVN + 384 + c);
            const __half2* vp = (const __half2*)(base + (size_t)r * QKVN + 768 + c);
            float2 k0 = __half22float2(kp[0]), k1 = __half22float2(kp[1]);
            float2 v0 = __half22float2(vp[0]), v1 = __half22float2(vp[1]);
            *(float4*)&ks[r][c] = make_float4(k0.x, k0.y, k1.x, k1.y);
            *(float4*)&vs[r][c] = make_float4(v0.x, v0.y, v1.x, v1.y);
        }
        __syncthreads();
        #pragma unroll 8
        for (int r = 0; r < 64; r++) {
            const float4 a  = *(const float4*)&ks[r][d0];
            const float4 bb = *(const float4*)&vs[r][e0];
            acc[0][0] += a.x * bb.x; acc[0][1] += a.x * bb.y; acc[0][2] += a.x * bb.z; acc[0][3] += a.x * bb.w;
            acc[1][0] += a.y * bb.x; acc[1][1] += a.y * bb.y; acc[1][2] += a.y * bb.z; acc[1][3] += a.y * bb.w;
            acc[2][0] += a.z * bb.x; acc[2][1] += a.z * bb.y; acc[2][2] += a.z * bb.z; acc[2][3] += a.z * bb.w;
            acc[3][0] += a.w * bb.x; acc[3][1] += a.w * bb.y; acc[3][2] += a.w * bb.z; acc[3][3] += a.w * bb.w;
        }
        if (tid < 64) {
            #pragma unroll
            for (int r = 0; r < 64; r++) ksacc += ks[r][tid];
        }
        __syncthreads();
    }

    float* kvp = g_kv + bh * (HD * HD);
    #pragma unroll
    for (int i = 0; i < 4; i++)
        #pragma unroll
        for (int j = 0; j < 4; j++)
            atomicAdd(&kvp[(d0 + i) * HD + (e0 + j)], acc[i][j]);
    if (tid < 64) atomicAdd(&g_ksum[bh * HD + tid], ksacc);
}

// ---------------- attn: o[n,e] = z[n] * sum_d q[n,d] * kv[d,e], fp16 in/out ----------------
__global__ __launch_bounds__(256) void attn_kernel()
{
    const int bh = blockIdx.y;
    const int b  = bh / NH, h = bh % NH;
    const int nbase = blockIdx.x * 64;

    __shared__ float qs[64][64];
    __shared__ float kvs[64][64];
    __shared__ float kss[64];
    __shared__ float zs[64];

    const int tid = threadIdx.x;

    for (int i = tid; i < 1024; i += 256) {
        const int r = i >> 4, c = (i & 15) << 2;
        *(float4*)&kvs[r][c] = *(const float4*)(g_kv + bh * (HD * HD) + r * HD + c);
    }
    if (tid < 64) kss[tid] = g_ksum[bh * HD + tid];

    const __half* qbase = g_qkv + (size_t)(b * SEQ + nbase) * QKVN + h * HD;
    for (int i = tid; i < 1024; i += 256) {
        const int r = i >> 4, c = (i & 15) << 2;
        const __half2* qp = (const __half2*)(qbase + (size_t)r * QKVN + c);
        float2 q0 = __half22float2(qp[0]), q1 = __half22float2(qp[1]);
        *(float4*)&qs[r][c] = make_float4(q0.x, q0.y, q1.x, q1.y);
    }
    __syncthreads();

    if (tid < 64) {
        float dot = 0.f;
        #pragma unroll
        for (int d = 0; d < 64; d++) dot += qs[tid][d] * kss[d];
        zs[tid] = 1.f / (dot + 1e-6f);
    }
    __syncthreads();

    const int tx = tid & 15, ty = tid >> 4;
    const int e0 = tx * 4, r0 = ty * 4;
    float acc[4][4] = {};
    #pragma unroll 8
    for (int d = 0; d < 64; d++) {
        const float4 bb = *(const float4*)&kvs[d][e0];
        const float a0 = qs[r0 + 0][d];
        const float a1 = qs[r0 + 1][d];
        const float a2 = qs[r0 + 2][d];
        const float a3 = qs[r0 + 3][d];
        acc[0][0] += a0 * bb.x; acc[0][1] += a0 * bb.y; acc[0][2] += a0 * bb.z; acc[0][3] += a0 * bb.w;
        acc[1][0] += a1 * bb.x; acc[1][1] += a1 * bb.y; acc[1][2] += a1 * bb.z; acc[1][3] += a1 * bb.w;
        acc[2][0] += a2 * bb.x; acc[2][1] += a2 * bb.y; acc[2][2] += a2 * bb.z; acc[2][3] += a2 * bb.w;
        acc[3][0] += a3 * bb.x; acc[3][1] += a3 * bb.y; acc[3][2] += a3 * bb.z; acc[3][3] += a3 * bb.w;
    }

    #pragma unroll
    for (int i = 0; i < 4; i++) {
        const float z = zs[r0 + i];
        __half2* op = (__half2*)(g_attn + (size_t)(b * SEQ + nbase + r0 + i) * DIM + h * HD + e0);
        op[0] = __floats2half2_rn(acc[i][0] * z, acc[i][1] * z);
        op[1] = __floats2half2_rn(acc[i][2] * z, acc[i][3] * z);
    }
}

// ---------------- launch ----------------
extern "C" void kernel_launch(void* const* d_in, const int* in_sizes, int n_in,
                              void* d_out, int out_size)
{
    const float* x      = (const float*)d_in[0];
    const float* n1g    = (const float*)d_in[1];
    const float* n1b    = (const float*)d_in[2];
    const float* qkv_w  = (const float*)d_in[3];
    const float* qkv_b  = (const float*)d_in[4];
    const float* proj_w = (const float*)d_in[5];
    const float* proj_b = (const float*)d_in[6];
    const float* n2g    = (const float*)d_in[7];
    const float* n2b    = (const float*)d_in[8];
    const float* fc1_w  = (const float*)d_in[9];
    const float* fc1_b  = (const float*)d_in[10];
    const float* fc2_w  = (const float*)d_in[11];
    const float* fc2_b  = (const float*)d_in[12];
    float* out = (float*)d_out;

    void *p_ln, *p_qkv, *p_attn, *p_x1, *p_mlp, *p_wq, *p_wp, *p_w1, *p_w2;
    cudaGetSymbolAddress(&p_ln,   g_ln);
    cudaGetSymbolAddress(&p_qkv,  g_qkv);
    cudaGetSymbolAddress(&p_attn, g_attn);
    cudaGetSymbolAddress(&p_x1,   g_x1);
    cudaGetSymbolAddress(&p_mlp,  g_mlp);
    cudaGetSymbolAddress(&p_wq,   g_wq);
    cudaGetSymbolAddress(&p_wp,   g_wp);
    cudaGetSymbolAddress(&p_w1,   g_w1);
    cudaGetSymbolAddress(&p_w2,   g_w2);
    __half* ln   = (__half*)p_ln;
    __half* qkv  = (__half*)p_qkv;
    __half* attn = (__half*)p_attn;
    float*  x1   = (float*)p_x1;
    __half* mlp  = (__half*)p_mlp;
    __half* wq   = (__half*)p_wq;
    __half* wp   = (__half*)p_wp;
    __half* w1   = (__half*)p_w1;
    __half* w2   = (__half*)p_w2;

    cudaFuncSetAttribute(gemm_f16<0>, cudaFuncAttributeMaxDynamicSharedMemorySize, GEMM_SMEM_BYTES);
    cudaFuncSetAttribute(gemm_f16<1>, cudaFuncAttributeMaxDynamicSharedMemorySize, GEMM_SMEM_BYTES);
    cudaFuncSetAttribute(gemm_f16<2>, cudaFuncAttributeMaxDynamicSharedMemorySize, GEMM_SMEM_BYTES);
    cudaFuncSetAttribute(gemm_f16<3>, cudaFuncAttributeMaxDynamicSharedMemorySize, GEMM_SMEM_BYTES);

    // 0. convert all weights to fp16 (single launch)
    cvt_all_w_kernel<<<(CVT_TOTAL4 + 255) / 256, 256>>>(qkv_w, proj_w, fc1_w, fc2_w);

    // 1. LN1 (fp16 out)
    ln_kernel<<<M_TOK / 8, 256>>>(x, n1g, n1b, ln);
    // 2. qkv GEMM + bias + phi on q,k (fp16 out)
    gemm_f16<0><<<dim3(QKVN / BN, M_TOK / BM), 256, GEMM_SMEM_BYTES>>>(ln, wq, qkv_b, nullptr, qkv, QKVN, DIM);
    // 3. zero kv state, then accumulate kv = K^T V and ksum per (b,h)
    zero_kv_kernel<<<(BH * HD * HD + 255) / 256, 256>>>();
    kv_kernel<<<dim3(SEQ / KV_CHUNK, BH), 256>>>();
    // 4. attn = (q @ kv) * z (fp16 out)
    attn_kernel<<<dim3(SEQ / 64, BH), 256>>>();
    // 5. proj GEMM + bias + residual(x) -> x1 (fp32)
    gemm_f16<1><<<dim3(DIM / BN, M_TOK / BM), 256, GEMM_SMEM_BYTES>>>(attn, wp, proj_b, x, x1, DIM, DIM);
    // 6. LN2 (fp16 out)
    ln_kernel<<<M_TOK / 8, 256>>>(x1, n2g, n2b, ln);
    // 7. fc1 GEMM + bias + gelu (fp16 out)
    gemm_f16<2><<<dim3(HID / BN, M_TOK / BM), 256, GEMM_SMEM_BYTES>>>(ln, w1, fc1_b, nullptr, mlp, HID, DIM);
    // 8. fc2 GEMM + bias + residual(x1) -> out (fp32)
    gemm_f16<3><<<dim3(DIM / BN, M_TOK / BM), 256, GEMM_SMEM_BYTES>>>(mlp, w2, fc2_b, x1, out, DIM, HID);
}

// round 14
// speedup vs baseline: 1.1623x; 1.1623x over previous
#include <cuda_runtime.h>
#include <cuda_fp16.h>
#include <math.h>
#include <stdint.h>

// ---------------- problem constants ----------------
#define M_TOK 32768          // 8 * 4096 tokens
#define SEQ   4096
#define DIM   384
#define NH    6
#define HD    64
#define BH    48             // batch*heads
#define QKVN  1152
#define HID   1536

// ---------------- scratch (static device arrays; no allocation) ----------------
__device__ __half g_ln  [(size_t)M_TOK * DIM];
__device__ __half g_qkv [(size_t)M_TOK * QKVN];
__device__ __half g_attn[(size_t)M_TOK * DIM];
__device__ float  g_x1  [(size_t)M_TOK * DIM];
__device__ __half g_mlp [(size_t)M_TOK * HID];
__device__ float  g_kv  [BH * HD * HD];
__device__ float  g_ksum[BH * HD];
__device__ __half g_wq [DIM * QKVN];
__device__ __half g_wp [DIM * DIM];
__device__ __half g_w1 [DIM * HID];
__device__ __half g_w2 [HID * DIM];

// ---------------- shared PTX helpers ----------------
__device__ __forceinline__ void cp16h(__half* dst, const __half* src) {
    uint32_t s = (uint32_t)__cvta_generic_to_shared(dst);
    asm volatile("cp.async.cg.shared.global [%0], [%1], 16;" :: "r"(s), "l"(src));
}
__device__ __forceinline__ void ldsm_x4(uint32_t* r, const __half* p) {
    uint32_t a = (uint32_t)__cvta_generic_to_shared(p);
    asm volatile("ldmatrix.sync.aligned.m8n8.x4.shared.b16 {%0,%1,%2,%3}, [%4];"
        : "=r"(r[0]), "=r"(r[1]), "=r"(r[2]), "=r"(r[3]) : "r"(a));
}
__device__ __forceinline__ void ldsm_x4_t(uint32_t* r, const __half* p) {
    uint32_t a = (uint32_t)__cvta_generic_to_shared(p);
    asm volatile("ldmatrix.sync.aligned.m8n8.x4.trans.shared.b16 {%0,%1,%2,%3}, [%4];"
        : "=r"(r[0]), "=r"(r[1]), "=r"(r[2]), "=r"(r[3]) : "r"(a));
}
__device__ __forceinline__ void mma_f16(float* d, const uint32_t* a, const uint32_t* b) {
    asm volatile(
        "mma.sync.aligned.m16n8k16.row.col.f32.f16.f16.f32 "
        "{%0,%1,%2,%3}, {%4,%5,%6,%7}, {%8,%9}, {%0,%1,%2,%3};"
        : "+f"(d[0]), "+f"(d[1]), "+f"(d[2]), "+f"(d[3])
        : "r"(a[0]), "r"(a[1]), "r"(a[2]), "r"(a[3]), "r"(b[0]), "r"(b[1]));
}
__device__ __forceinline__ float fast_gelu(float v) {
    const float two_u = 1.5957691216057308f * (v + 0.044715f * v * v * v);
    return v * (1.f / (1.f + __expf(-two_u)));
}

// ---------------- convert ALL weight matrices to fp16 in one launch ----------------
#define CVT_TOTAL4 442368
__global__ __launch_bounds__(256) void cvt_all_w_kernel(
    const float* __restrict__ qkv_w, const float* __restrict__ proj_w,
    const float* __restrict__ fc1_w, const float* __restrict__ fc2_w)
{
    const int i = blockIdx.x * 256 + threadIdx.x;
    if (i >= CVT_TOTAL4) return;
    const float* src;
    __half* dst;
    int off;
    if (i < 110592)      { src = qkv_w;  dst = g_wq; off = i; }
    else if (i < 147456) { src = proj_w; dst = g_wp; off = i - 110592; }
    else if (i < 294912) { src = fc1_w;  dst = g_w1; off = i - 147456; }
    else                 { src = fc2_w;  dst = g_w2; off = i - 294912; }
    float4 v = ((const float4*)src)[off];
    __half2* d = (__half2*)(dst + (size_t)off * 4);
    d[0] = __floats2half2_rn(v.x, v.y);
    d[1] = __floats2half2_rn(v.z, v.w);
}

// ---------------- LayerNorm: warp per row, fp16 output ----------------
__global__ __launch_bounds__(256) void ln_kernel(
    const float* __restrict__ x, const float* __restrict__ gma,
    const float* __restrict__ bta, __half* __restrict__ out)
{
    const int warp = threadIdx.x >> 5;
    const int lane = threadIdx.x & 31;
    const int row  = blockIdx.x * 8 + warp;
    const float4* xr = (const float4*)(x + (size_t)row * DIM);
    const float4* g4 = (const float4*)gma;
    const float4* b4 = (const float4*)bta;

    float4 v[3];
    #pragma unroll
    for (int i = 0; i < 3; i++) v[i] = xr[lane + i * 32];

    float s = 0.f, sq = 0.f;
    #pragma unroll
    for (int i = 0; i < 3; i++) {
        s  += v[i].x + v[i].y + v[i].z + v[i].w;
        sq += v[i].x*v[i].x + v[i].y*v[i].y + v[i].z*v[i].z + v[i].w*v[i].w;
    }
    #pragma unroll
    for (int o = 16; o > 0; o >>= 1) {
        s  += __shfl_xor_sync(0xffffffffu, s,  o);
        sq += __shfl_xor_sync(0xffffffffu, sq, o);
    }
    const float mean = s * (1.f / DIM);
    const float inv  = rsqrtf(sq * (1.f / DIM) - mean * mean + 1e-5f);

    #pragma unroll
    for (int i = 0; i < 3; i++) {
        const float4 gg = g4[lane + i * 32];
        const float4 bb = b4[lane + i * 32];
        __half2* d = (__half2*)(out + (size_t)row * DIM + (lane + i * 32) * 4);
        d[0] = __floats2half2_rn((v[i].x - mean) * inv * gg.x + bb.x,
                                 (v[i].y - mean) * inv * gg.y + bb.y);
        d[1] = __floats2half2_rn((v[i].z - mean) * inv * gg.z + bb.z,
                                 (v[i].w - mean) * inv * gg.w + bb.w);
    }
}

// ---------------- fp16 tensor-core GEMM, cp.async 3-stage pipeline ----------------
#define BM 128
#define BN 128
#define BK 32
#define STAGES 3
#define AS_STRIDE 40
#define BS_STRIDE 136
#define AS_BUF (BM * AS_STRIDE)
#define BS_BUF (BK * BS_STRIDE)
#define GEMM_SMEM_BYTES (STAGES * (AS_BUF + BS_BUF) * 2)   // 56832

template<int MODE>
__global__ __launch_bounds__(256, 2) void gemm_f16(
    const __half* __restrict__ A, const __half* __restrict__ W,
    const float* __restrict__ bias, const float* __restrict__ res,
    void* __restrict__ Cout, int N, int K)
{
    extern __shared__ __align__(16) __half smem_h[];
    __half* As = smem_h;
    __half* Bs = smem_h + STAGES * AS_BUF;

    const int tid  = threadIdx.x;
    const int lane = tid & 31;
    const int warp = tid >> 5;
    const int wm = warp >> 2;
    const int wn = warp & 3;
    const int g  = lane >> 2;
    const int tg = lane & 3;

    const int lm_r = ((lane >> 3) & 1) * 8 + (lane & 7);
    const int lm_c = (lane >> 4) * 8;

    const int bm = blockIdx.y * BM;
    const int bn = blockIdx.x * BN;
    const int T  = K / BK;

    auto stage = [&](int t) {
        const int s  = t % STAGES;
        const int kt = t * BK;
        __half* Ad = As + s * AS_BUF;
        __half* Bd = Bs + s * BS_BUF;
        #pragma unroll
        for (int i = 0; i < 2; i++) {
            const int idx = tid + i * 256;
            const int m = idx >> 2, c = (idx & 3) * 8;
            cp16h(&Ad[m * AS_STRIDE + c], A + (size_t)(bm + m) * K + kt + c);
        }
        #pragma unroll
        for (int i = 0; i < 2; i++) {
            const int idx = tid + i * 256;
            const int k = idx >> 4, c = (idx & 15) * 8;
            cp16h(&Bd[k * BS_STRIDE + c], W + (size_t)(kt + k) * N + bn + c);
        }
        asm volatile("cp.async.commit_group;");
    };

    stage(0);
    stage(1);

    float acc[4][4][4] = {};
    const int m_base = wm * 64;
    const int n_base = wn * 32;

    int buf = 0;
    for (int t = 0; t < T; t++) {
        asm volatile("cp.async.wait_group 1;");
        __syncthreads();

        const __half* Ab = As + buf * AS_BUF;
        const __half* Bb = Bs + buf * BS_BUF;

        #pragma unroll
        for (int ks = 0; ks < 2; ks++) {
            const int k0 = ks * 16;
            uint32_t af[4][4], bf[4][2];
            #pragma unroll
            for (int mt = 0; mt < 4; mt++)
                ldsm_x4(af[mt], Ab + (m_base + mt * 16 + lm_r) * AS_STRIDE + k0 + lm_c);
            #pragma unroll
            for (int np = 0; np < 2; np++) {
                uint32_t r[4];
                ldsm_x4_t(r, Bb + (k0 + lm_r) * BS_STRIDE + n_base + np * 16 + lm_c);
                bf[np * 2    ][0] = r[0]; bf[np * 2    ][1] = r[1];
                bf[np * 2 + 1][0] = r[2]; bf[np * 2 + 1][1] = r[3];
            }
            #pragma unroll
            for (int mt = 0; mt < 4; mt++)
                #pragma unroll
                for (int nt = 0; nt < 4; nt++)
                    mma_f16(acc[mt][nt], af[mt], bf[nt]);
        }

        if (t + 2 < T) stage(t + 2);
        else asm volatile("cp.async.commit_group;");

        buf = (buf + 1 == STAGES) ? 0 : buf + 1;
    }

    float*  Cf = (float*)Cout;
    __half* Ch = (__half*)Cout;
    #pragma unroll
    for (int mt = 0; mt < 4; mt++) {
        #pragma unroll
        for (int half_i = 0; half_i < 2; half_i++) {
            const int row = bm + m_base + mt * 16 + g + half_i * 8;
            #pragma unroll
            for (int nt = 0; nt < 4; nt++) {
                const int col = bn + n_base + nt * 8 + tg * 2;
                float v0 = acc[mt][nt][half_i * 2 + 0] + bias[col];
                float v1 = acc[mt][nt][half_i * 2 + 1] + bias[col + 1];
                if (MODE == 0) {
                    if (col     < 768) v0 = (v0 > 0.f) ? (v0 + 1.f) : __expf(v0);
                    if (col + 1 < 768) v1 = (v1 > 0.f) ? (v1 + 1.f) : __expf(v1);
                    *(__half2*)(Ch + (size_t)row * N + col) = __floats2half2_rn(v0, v1);
                }
                if (MODE == 1 || MODE == 3) {
                    const float2 r = *(const float2*)(res + (size_t)row * N + col);
                    v0 += r.x; v1 += r.y;
                    *(float2*)(Cf + (size_t)row * N + col) = make_float2(v0, v1);
                }
                if (MODE == 2) {
                    v0 = fast_gelu(v0);
                    v1 = fast_gelu(v1);
                    *(__half2*)(Ch + (size_t)row * N + col) = __floats2half2_rn(v0, v1);
                }
            }
        }
    }
}

// ---------------- zero kv state ----------------
__global__ void zero_kv_kernel()
{
    const int i = blockIdx.x * blockDim.x + threadIdx.x;
    if (i < BH * HD * HD) g_kv[i] = 0.f;
    if (i < BH * HD)      g_ksum[i] = 0.f;
}

// ---------------- kv-state via tensor cores: kv = K^T V over 512-token chunks ----------------
#define KVC 512
#define KT_STRIDE 72
__global__ __launch_bounds__(128) void kv_kernel()
{
    const int bh = blockIdx.y;
    const int b  = bh / NH, h = bh % NH;
    const int nbase = blockIdx.x * KVC;

    __shared__ __half ks[2][64][KT_STRIDE];
    __shared__ __half vs[2][64][KT_STRIDE];

    const int tid  = threadIdx.x;
    const int lane = tid & 31;
    const int warp = tid >> 5;           // 0..3, owns d-rows 16*warp..+15
    const int g  = lane >> 2;
    const int tg = lane & 3;
    const int lm_r = ((lane >> 3) & 1) * 8 + (lane & 7);
    const int lm_c = (lane >> 4) * 8;

    auto stage = [&](int tt, int buf) {
        const __half* base = g_qkv + (size_t)(b * SEQ + nbase + tt * 64) * QKVN + h * HD;
        #pragma unroll
        for (int i = 0; i < 4; i++) {
            const int idx = tid + i * 128;
            const int r = idx >> 3, c = (idx & 7) * 8;
            cp16h(&ks[buf][r][c], base + (size_t)r * QKVN + 384 + c);
            cp16h(&vs[buf][r][c], base + (size_t)r * QKVN + 768 + c);
        }
        asm volatile("cp.async.commit_group;");
    };

    stage(0, 0);
    stage(1, 1);

    float acc[8][4] = {};
    float ksacc = 0.f;
    const int d_sum  = tid >> 1;          // 0..63
    const int r_half = (tid & 1) * 32;

    for (int tt = 0; tt < KVC / 64; tt++) {
        asm volatile("cp.async.wait_group 1;");
        __syncthreads();
        const int buf = tt & 1;

        // ksum partial (k column sums)
        #pragma unroll 8
        for (int r = 0; r < 32; r++)
            ksacc += __half2float(ks[buf][r_half + r][d_sum]);

        // mma: C[d][e] += K^T V ; A-frags from trans-ldsm of k (reorder {0,2,1,3})
        #pragma unroll
        for (int kstep = 0; kstep < 4; kstep++) {
            const int t0 = kstep * 16;
            uint32_t rr[4], af[4], bf[4][2];
            ldsm_x4_t(rr, &ks[buf][t0 + lm_r][16 * warp + lm_c]);
            af[0] = rr[0]; af[1] = rr[2]; af[2] = rr[1]; af[3] = rr[3];
            #pragma unroll
            for (int np = 0; np < 4; np++) {
                uint32_t r2[4];
                ldsm_x4_t(r2, &vs[buf][t0 + lm_r][np * 16 + lm_c]);
                bf[0][0] = r2[0]; bf[0][1] = r2[1];
                bf[1][0] = r2[2]; bf[1][1] = r2[3];
                mma_f16(acc[np * 2    ], af, bf[0]);
                mma_f16(acc[np * 2 + 1], af, bf[1]);
            }
        }

        __syncthreads();   // all reads of buf done before restaging it
        if (tt + 2 < KVC / 64) stage(tt + 2, buf);
        else asm volatile("cp.async.commit_group;");
    }

    // reduce + atomics
    float* kvp = g_kv + bh * (HD * HD);
    #pragma unroll
    for (int nt = 0; nt < 8; nt++) {
        #pragma unroll
        for (int half_i = 0; half_i < 2; half_i++) {
            const int d = 16 * warp + g + half_i * 8;
            const int e = nt * 8 + tg * 2;
            atomicAdd(&kvp[d * HD + e    ], acc[nt][half_i * 2 + 0]);
            atomicAdd(&kvp[d * HD + e + 1], acc[nt][half_i * 2 + 1]);
        }
    }
    ksacc += __shfl_xor_sync(0xffffffffu, ksacc, 1);
    if ((tid & 1) == 0) atomicAdd(&g_ksum[bh * HD + d_sum], ksacc);
}

// ---------------- attn via tensor cores: o = (Q @ KV) * z ----------------
__global__ __launch_bounds__(128) void attn_kernel()
{
    const int bh = blockIdx.y;
    const int b  = bh / NH, h = bh % NH;
    const int nbase = blockIdx.x * 64;

    __shared__ __half qs [64][KT_STRIDE];
    __shared__ __half kvh[64][KT_STRIDE];
    __shared__ float kss[64];
    __shared__ float zs[64];

    const int tid  = threadIdx.x;
    const int lane = tid & 31;
    const int warp = tid >> 5;           // token rows 16*warp..+15
    const int g  = lane >> 2;
    const int tg = lane & 3;
    const int lm_r = ((lane >> 3) & 1) * 8 + (lane & 7);
    const int lm_c = (lane >> 4) * 8;

    // stage q tile (fp16, cp.async)
    {
        const __half* base = g_qkv + (size_t)(b * SEQ + nbase) * QKVN + h * HD;
        #pragma unroll
        for (int i = 0; i < 4; i++) {
            const int idx = tid + i * 128;
            const int r = idx >> 3, c = (idx & 7) * 8;
            cp16h(&qs[r][c], base + (size_t)r * QKVN + c);
        }
        asm volatile("cp.async.commit_group;");
    }
    // kv state fp32 -> fp16 smem
    {
        const float2* kvp = (const float2*)(g_kv + bh * (HD * HD));
        #pragma unroll
        for (int i = 0; i < 16; i++) {
            const int idx = tid + i * 128;
            const int r = idx >> 5, c = (idx & 31) * 2;
            float2 v = kvp[idx];
            *(__half2*)&kvh[r][c] = __floats2half2_rn(v.x, v.y);
        }
    }
    if (tid < 64) kss[tid] = g_ksum[bh * HD + tid];
    asm volatile("cp.async.wait_group 0;");
    __syncthreads();

    // z per row
    {
        const int row = tid >> 1;
        const int d0 = (tid & 1) * 32;
        float dot = 0.f;
        #pragma unroll 8
        for (int j = 0; j < 32; j++)
            dot += __half2float(qs[row][d0 + j]) * kss[d0 + j];
        dot += __shfl_xor_sync(0xffffffffu, dot, 1);
        if ((tid & 1) == 0) zs[row] = 1.f / (dot + 1e-6f);
    }
    __syncthreads();

    // mma: M=16/warp, N=64, K=64
    float acc[8][4] = {};
    #pragma unroll
    for (int kstep = 0; kstep < 4; kstep++) {
        const int k0 = kstep * 16;
        uint32_t af[4];
        ldsm_x4(af, &qs[16 * warp + lm_r][k0 + lm_c]);
        #pragma unroll
        for (int np = 0; np < 4; np++) {
            uint32_t r2[4];
            uint32_t bf0[2], bf1[2];
            ldsm_x4_t(r2, &kvh[k0 + lm_r][np * 16 + lm_c]);
            bf0[0] = r2[0]; bf0[1] = r2[1];
            bf1[0] = r2[2]; bf1[1] = r2[3];
            mma_f16(acc[np * 2    ], af, bf0);
            mma_f16(acc[np * 2 + 1], af, bf1);
        }
    }

    // epilogue: scale by z, store fp16
    #pragma unroll
    for (int half_i = 0; half_i < 2; half_i++) {
        const int row = 16 * warp + g + half_i * 8;
        const float z = zs[row];
        __half* op = g_attn + (size_t)(b * SEQ + nbase + row) * DIM + h * HD;
        #pragma unroll
        for (int nt = 0; nt < 8; nt++) {
            const int e = nt * 8 + tg * 2;
            *(__half2*)(op + e) = __floats2half2_rn(acc[nt][half_i * 2 + 0] * z,
                                                    acc[nt][half_i * 2 + 1] * z);
        }
    }
}

// ---------------- launch ----------------
extern "C" void kernel_launch(void* const* d_in, const int* in_sizes, int n_in,
                              void* d_out, int out_size)
{
    const float* x      = (const float*)d_in[0];
    const float* n1g    = (const float*)d_in[1];
    const float* n1b    = (const float*)d_in[2];
    const float* qkv_w  = (const float*)d_in[3];
    const float* qkv_b  = (const float*)d_in[4];
    const float* proj_w = (const float*)d_in[5];
    const float* proj_b = (const float*)d_in[6];
    const float* n2g    = (const float*)d_in[7];
    const float* n2b    = (const float*)d_in[8];
    const float* fc1_w  = (const float*)d_in[9];
    const float* fc1_b  = (const float*)d_in[10];
    const float* fc2_w  = (const float*)d_in[11];
    const float* fc2_b  = (const float*)d_in[12];
    float* out = (float*)d_out;

    void *p_ln, *p_qkv, *p_attn, *p_x1, *p_mlp, *p_wq, *p_wp, *p_w1, *p_w2;
    cudaGetSymbolAddress(&p_ln,   g_ln);
    cudaGetSymbolAddress(&p_qkv,  g_qkv);
    cudaGetSymbolAddress(&p_attn, g_attn);
    cudaGetSymbolAddress(&p_x1,   g_x1);
    cudaGetSymbolAddress(&p_mlp,  g_mlp);
    cudaGetSymbolAddress(&p_wq,   g_wq);
    cudaGetSymbolAddress(&p_wp,   g_wp);
    cudaGetSymbolAddress(&p_w1,   g_w1);
    cudaGetSymbolAddress(&p_w2,   g_w2);
    __half* ln   = (__half*)p_ln;
    __half* qkv  = (__half*)p_qkv;
    __half* attn = (__half*)p_attn;
    float*  x1   = (float*)p_x1;
    __half* mlp  = (__half*)p_mlp;
    __half* wq   = (__half*)p_wq;
    __half* wp   = (__half*)p_wp;
    __half* w1   = (__half*)p_w1;
    __half* w2   = (__half*)p_w2;

    cudaFuncSetAttribute(gemm_f16<0>, cudaFuncAttributeMaxDynamicSharedMemorySize, GEMM_SMEM_BYTES);
    cudaFuncSetAttribute(gemm_f16<1>, cudaFuncAttributeMaxDynamicSharedMemorySize, GEMM_SMEM_BYTES);
    cudaFuncSetAttribute(gemm_f16<2>, cudaFuncAttributeMaxDynamicSharedMemorySize, GEMM_SMEM_BYTES);
    cudaFuncSetAttribute(gemm_f16<3>, cudaFuncAttributeMaxDynamicSharedMemorySize, GEMM_SMEM_BYTES);

    // 0. convert all weights to fp16 (single launch)
    cvt_all_w_kernel<<<(CVT_TOTAL4 + 255) / 256, 256>>>(qkv_w, proj_w, fc1_w, fc2_w);

    // 1. LN1 (fp16 out)
    ln_kernel<<<M_TOK / 8, 256>>>(x, n1g, n1b, ln);
    // 2. qkv GEMM + bias + phi on q,k (fp16 out)
    gemm_f16<0><<<dim3(QKVN / BN, M_TOK / BM), 256, GEMM_SMEM_BYTES>>>(ln, wq, qkv_b, nullptr, qkv, QKVN, DIM);
    // 3. zero kv state, then kv = K^T V (tensor cores) + ksum per (b,h)
    zero_kv_kernel<<<(BH * HD * HD + 255) / 256, 256>>>();
    kv_kernel<<<dim3(SEQ / KVC, BH), 128>>>();
    // 4. attn = (q @ kv) * z (tensor cores, fp16 out)
    attn_kernel<<<dim3(SEQ / 64, BH), 128>>>();
    // 5. proj GEMM + bias + residual(x) -> x1 (fp32)
    gemm_f16<1><<<dim3(DIM / BN, M_TOK / BM), 256, GEMM_SMEM_BYTES>>>(attn, wp, proj_b, x, x1, DIM, DIM);
    // 6. LN2 (fp16 out)
    ln_kernel<<<M_TOK / 8, 256>>>(x1, n2g, n2b, ln);
    // 7. fc1 GEMM + bias + gelu (fp16 out)
    gemm_f16<2><<<dim3(HID / BN, M_TOK / BM), 256, GEMM_SMEM_BYTES>>>(ln, w1, fc1_b, nullptr, mlp, HID, DIM);
    // 8. fc2 GEMM + bias + residual(x1) -> out (fp32)
    gemm_f16<3><<<dim3(DIM / BN, M_TOK / BM), 256, GEMM_SMEM_BYTES>>>(mlp, w2, fc2_b, x1, out, DIM, HID);
}

// round 15
// speedup vs baseline: 1.1754x; 1.0113x over previous
#include <cuda_runtime.h>
#include <cuda_fp16.h>
#include <math.h>
#include <stdint.h>

// ---------------- problem constants ----------------
#define M_TOK 32768          // 8 * 4096 tokens
#define SEQ   4096
#define DIM   384
#define NH    6
#define HD    64
#define BH    48             // batch*heads
#define QKVN  1152
#define HID   1536

// ---------------- scratch (static device arrays; no allocation) ----------------
__device__ __half g_ln  [(size_t)M_TOK * DIM];
__device__ __half g_qkv [(size_t)M_TOK * QKVN];
__device__ __half g_attn[(size_t)M_TOK * DIM];
__device__ __half g_x1  [(size_t)M_TOK * DIM];       // residual stream after attn (fp16)
__device__ __half g_mlp [(size_t)M_TOK * HID];
__device__ float  g_kv  [BH * HD * HD];
__device__ float  g_ksum[BH * HD];
__device__ __half g_wq [DIM * QKVN];
__device__ __half g_wp [DIM * DIM];
__device__ __half g_w1 [DIM * HID];
__device__ __half g_w2 [HID * DIM];

// ---------------- shared PTX helpers ----------------
__device__ __forceinline__ void cp16h(__half* dst, const __half* src) {
    uint32_t s = (uint32_t)__cvta_generic_to_shared(dst);
    asm volatile("cp.async.cg.shared.global [%0], [%1], 16;" :: "r"(s), "l"(src));
}
__device__ __forceinline__ void ldsm_x4(uint32_t* r, const __half* p) {
    uint32_t a = (uint32_t)__cvta_generic_to_shared(p);
    asm volatile("ldmatrix.sync.aligned.m8n8.x4.shared.b16 {%0,%1,%2,%3}, [%4];"
        : "=r"(r[0]), "=r"(r[1]), "=r"(r[2]), "=r"(r[3]) : "r"(a));
}
__device__ __forceinline__ void ldsm_x4_t(uint32_t* r, const __half* p) {
    uint32_t a = (uint32_t)__cvta_generic_to_shared(p);
    asm volatile("ldmatrix.sync.aligned.m8n8.x4.trans.shared.b16 {%0,%1,%2,%3}, [%4];"
        : "=r"(r[0]), "=r"(r[1]), "=r"(r[2]), "=r"(r[3]) : "r"(a));
}
__device__ __forceinline__ void mma_f16(float* d, const uint32_t* a, const uint32_t* b) {
    asm volatile(
        "mma.sync.aligned.m16n8k16.row.col.f32.f16.f16.f32 "
        "{%0,%1,%2,%3}, {%4,%5,%6,%7}, {%8,%9}, {%0,%1,%2,%3};"
        : "+f"(d[0]), "+f"(d[1]), "+f"(d[2]), "+f"(d[3])
        : "r"(a[0]), "r"(a[1]), "r"(a[2]), "r"(a[3]), "r"(b[0]), "r"(b[1]));
}
__device__ __forceinline__ float fast_gelu(float v) {
    const float two_u = 1.5957691216057308f * (v + 0.044715f * v * v * v);
    return v * (1.f / (1.f + __expf(-two_u)));
}
__device__ __forceinline__ float4 load4f(const float* p, int idx) {
    return ((const float4*)p)[idx];
}
__device__ __forceinline__ float4 load4f(const __half* p, int idx) {
    const __half2* h = (const __half2*)p + idx * 2;
    float2 a = __half22float2(h[0]), b = __half22float2(h[1]);
    return make_float4(a.x, a.y, b.x, b.y);
}

// ---------------- convert weights to fp16 + zero kv state, one launch ----------------
#define CVT_TOTAL4 442368
#define KV_ZERO4   ((BH * HD * HD) / 4)     // 36864
#define KSUM_ZERO4 ((BH * HD) / 4)          // 768
__global__ __launch_bounds__(256) void cvt_all_w_kernel(
    const float* __restrict__ qkv_w, const float* __restrict__ proj_w,
    const float* __restrict__ fc1_w, const float* __restrict__ fc2_w)
{
    const int i = blockIdx.x * 256 + threadIdx.x;
    if (i < KV_ZERO4)   ((float4*)g_kv)[i]   = make_float4(0.f, 0.f, 0.f, 0.f);
    if (i < KSUM_ZERO4) ((float4*)g_ksum)[i] = make_float4(0.f, 0.f, 0.f, 0.f);
    if (i >= CVT_TOTAL4) return;
    const float* src;
    __half* dst;
    int off;
    if (i < 110592)      { src = qkv_w;  dst = g_wq; off = i; }
    else if (i < 147456) { src = proj_w; dst = g_wp; off = i - 110592; }
    else if (i < 294912) { src = fc1_w;  dst = g_w1; off = i - 147456; }
    else                 { src = fc2_w;  dst = g_w2; off = i - 294912; }
    float4 v = ((const float4*)src)[off];
    __half2* d = (__half2*)(dst + (size_t)off * 4);
    d[0] = __floats2half2_rn(v.x, v.y);
    d[1] = __floats2half2_rn(v.z, v.w);
}

// ---------------- LayerNorm: warp per row, fp16 output, templated input ----------------
template<typename TIN>
__global__ __launch_bounds__(256) void ln_kernel(
    const TIN* __restrict__ x, const float* __restrict__ gma,
    const float* __restrict__ bta, __half* __restrict__ out)
{
    const int warp = threadIdx.x >> 5;
    const int lane = threadIdx.x & 31;
    const int row  = blockIdx.x * 8 + warp;
    const TIN* xr = x + (size_t)row * DIM;
    const float4* g4 = (const float4*)gma;
    const float4* b4 = (const float4*)bta;

    float4 v[3];
    #pragma unroll
    for (int i = 0; i < 3; i++) v[i] = load4f(xr, lane + i * 32);

    float s = 0.f, sq = 0.f;
    #pragma unroll
    for (int i = 0; i < 3; i++) {
        s  += v[i].x + v[i].y + v[i].z + v[i].w;
        sq += v[i].x*v[i].x + v[i].y*v[i].y + v[i].z*v[i].z + v[i].w*v[i].w;
    }
    #pragma unroll
    for (int o = 16; o > 0; o >>= 1) {
        s  += __shfl_xor_sync(0xffffffffu, s,  o);
        sq += __shfl_xor_sync(0xffffffffu, sq, o);
    }
    const float mean = s * (1.f / DIM);
    const float inv  = rsqrtf(sq * (1.f / DIM) - mean * mean + 1e-5f);

    #pragma unroll
    for (int i = 0; i < 3; i++) {
        const float4 gg = g4[lane + i * 32];
        const float4 bb = b4[lane + i * 32];
        __half2* d = (__half2*)(out + (size_t)row * DIM + (lane + i * 32) * 4);
        d[0] = __floats2half2_rn((v[i].x - mean) * inv * gg.x + bb.x,
                                 (v[i].y - mean) * inv * gg.y + bb.y);
        d[1] = __floats2half2_rn((v[i].z - mean) * inv * gg.z + bb.z,
                                 (v[i].w - mean) * inv * gg.w + bb.w);
    }
}

// ---------------- fp16 tensor-core GEMM, cp.async 3-stage pipeline ----------------
//   MODE 0: qkv  -> phi on cols<768, fp16 out
//   MODE 1: proj -> +res (fp32 x), fp16 out (x1)
//   MODE 2: fc1  -> gelu, fp16 out
//   MODE 3: fc2  -> +res (fp16 x1), fp32 out
#define BM 128
#define BN 128
#define BK 32
#define STAGES 3
#define AS_STRIDE 40
#define BS_STRIDE 136
#define AS_BUF (BM * AS_STRIDE)
#define BS_BUF (BK * BS_STRIDE)
#define GEMM_SMEM_BYTES (STAGES * (AS_BUF + BS_BUF) * 2)   // 56832

template<int MODE>
__global__ __launch_bounds__(256, 2) void gemm_f16(
    const __half* __restrict__ A, const __half* __restrict__ W,
    const float* __restrict__ bias, const void* __restrict__ res,
    void* __restrict__ Cout, int N, int K)
{
    extern __shared__ __align__(16) __half smem_h[];
    __half* As = smem_h;
    __half* Bs = smem_h + STAGES * AS_BUF;

    const int tid  = threadIdx.x;
    const int lane = tid & 31;
    const int warp = tid >> 5;
    const int wm = warp >> 2;
    const int wn = warp & 3;
    const int g  = lane >> 2;
    const int tg = lane & 3;

    const int lm_r = ((lane >> 3) & 1) * 8 + (lane & 7);
    const int lm_c = (lane >> 4) * 8;

    const int bm = blockIdx.y * BM;
    const int bn = blockIdx.x * BN;
    const int T  = K / BK;

    auto stage = [&](int t) {
        const int s  = t % STAGES;
        const int kt = t * BK;
        __half* Ad = As + s * AS_BUF;
        __half* Bd = Bs + s * BS_BUF;
        #pragma unroll
        for (int i = 0; i < 2; i++) {
            const int idx = tid + i * 256;
            const int m = idx >> 2, c = (idx & 3) * 8;
            cp16h(&Ad[m * AS_STRIDE + c], A + (size_t)(bm + m) * K + kt + c);
        }
        #pragma unroll
        for (int i = 0; i < 2; i++) {
            const int idx = tid + i * 256;
            const int k = idx >> 4, c = (idx & 15) * 8;
            cp16h(&Bd[k * BS_STRIDE + c], W + (size_t)(kt + k) * N + bn + c);
        }
        asm volatile("cp.async.commit_group;");
    };

    stage(0);
    stage(1);

    float acc[4][4][4] = {};
    const int m_base = wm * 64;
    const int n_base = wn * 32;

    int buf = 0;
    for (int t = 0; t < T; t++) {
        asm volatile("cp.async.wait_group 1;");
        __syncthreads();

        const __half* Ab = As + buf * AS_BUF;
        const __half* Bb = Bs + buf * BS_BUF;

        #pragma unroll
        for (int ks = 0; ks < 2; ks++) {
            const int k0 = ks * 16;
            uint32_t af[4][4], bf[4][2];
            #pragma unroll
            for (int mt = 0; mt < 4; mt++)
                ldsm_x4(af[mt], Ab + (m_base + mt * 16 + lm_r) * AS_STRIDE + k0 + lm_c);
            #pragma unroll
            for (int np = 0; np < 2; np++) {
                uint32_t r[4];
                ldsm_x4_t(r, Bb + (k0 + lm_r) * BS_STRIDE + n_base + np * 16 + lm_c);
                bf[np * 2    ][0] = r[0]; bf[np * 2    ][1] = r[1];
                bf[np * 2 + 1][0] = r[2]; bf[np * 2 + 1][1] = r[3];
            }
            #pragma unroll
            for (int mt = 0; mt < 4; mt++)
                #pragma unroll
                for (int nt = 0; nt < 4; nt++)
                    mma_f16(acc[mt][nt], af[mt], bf[nt]);
        }

        if (t + 2 < T) stage(t + 2);
        else asm volatile("cp.async.commit_group;");

        buf = (buf + 1 == STAGES) ? 0 : buf + 1;
    }

    float*  Cf = (float*)Cout;
    __half* Ch = (__half*)Cout;
    const float*  resf = (const float*)res;
    const __half* resh = (const __half*)res;
    #pragma unroll
    for (int mt = 0; mt < 4; mt++) {
        #pragma unroll
        for (int half_i = 0; half_i < 2; half_i++) {
            const int row = bm + m_base + mt * 16 + g + half_i * 8;
            #pragma unroll
            for (int nt = 0; nt < 4; nt++) {
                const int col = bn + n_base + nt * 8 + tg * 2;
                float v0 = acc[mt][nt][half_i * 2 + 0] + bias[col];
                float v1 = acc[mt][nt][half_i * 2 + 1] + bias[col + 1];
                if (MODE == 0) {
                    if (col     < 768) v0 = (v0 > 0.f) ? (v0 + 1.f) : __expf(v0);
                    if (col + 1 < 768) v1 = (v1 > 0.f) ? (v1 + 1.f) : __expf(v1);
                    *(__half2*)(Ch + (size_t)row * N + col) = __floats2half2_rn(v0, v1);
                }
                if (MODE == 1) {   // +res fp32, out fp16 (x1)
                    const float2 r = *(const float2*)(resf + (size_t)row * N + col);
                    v0 += r.x; v1 += r.y;
                    *(__half2*)(Ch + (size_t)row * N + col) = __floats2half2_rn(v0, v1);
                }
                if (MODE == 2) {
                    v0 = fast_gelu(v0);
                    v1 = fast_gelu(v1);
                    *(__half2*)(Ch + (size_t)row * N + col) = __floats2half2_rn(v0, v1);
                }
                if (MODE == 3) {   // +res fp16 (x1), out fp32
                    const float2 r = __half22float2(*(const __half2*)(resh + (size_t)row * N + col));
                    v0 += r.x; v1 += r.y;
                    *(float2*)(Cf + (size_t)row * N + col) = make_float2(v0, v1);
                }
            }
        }
    }
}

// ---------------- kv-state via tensor cores: kv = K^T V over 512-token chunks ----------------
#define KVC 512
#define KT_STRIDE 72
__global__ __launch_bounds__(128) void kv_kernel()
{
    const int bh = blockIdx.y;
    const int b  = bh / NH, h = bh % NH;
    const int nbase = blockIdx.x * KVC;

    __shared__ __half ks[2][64][KT_STRIDE];
    __shared__ __half vs[2][64][KT_STRIDE];

    const int tid  = threadIdx.x;
    const int lane = tid & 31;
    const int warp = tid >> 5;
    const int g  = lane >> 2;
    const int tg = lane & 3;
    const int lm_r = ((lane >> 3) & 1) * 8 + (lane & 7);
    const int lm_c = (lane >> 4) * 8;

    auto stage = [&](int tt, int buf) {
        const __half* base = g_qkv + (size_t)(b * SEQ + nbase + tt * 64) * QKVN + h * HD;
        #pragma unroll
        for (int i = 0; i < 4; i++) {
            const int idx = tid + i * 128;
            const int r = idx >> 3, c = (idx & 7) * 8;
            cp16h(&ks[buf][r][c], base + (size_t)r * QKVN + 384 + c);
            cp16h(&vs[buf][r][c], base + (size_t)r * QKVN + 768 + c);
        }
        asm volatile("cp.async.commit_group;");
    };

    stage(0, 0);
    stage(1, 1);

    float acc[8][4] = {};
    float ksacc = 0.f;
    const int d_sum  = tid >> 1;
    const int r_half = (tid & 1) * 32;

    for (int tt = 0; tt < KVC / 64; tt++) {
        asm volatile("cp.async.wait_group 1;");
        __syncthreads();
        const int buf = tt & 1;

        #pragma unroll 8
        for (int r = 0; r < 32; r++)
            ksacc += __half2float(ks[buf][r_half + r][d_sum]);

        #pragma unroll
        for (int kstep = 0; kstep < 4; kstep++) {
            const int t0 = kstep * 16;
            uint32_t rr[4], af[4], bf[4][2];
            ldsm_x4_t(rr, &ks[buf][t0 + lm_r][16 * warp + lm_c]);
            af[0] = rr[0]; af[1] = rr[2]; af[2] = rr[1]; af[3] = rr[3];
            #pragma unroll
            for (int np = 0; np < 4; np++) {
                uint32_t r2[4];
                ldsm_x4_t(r2, &vs[buf][t0 + lm_r][np * 16 + lm_c]);
                bf[0][0] = r2[0]; bf[0][1] = r2[1];
                bf[1][0] = r2[2]; bf[1][1] = r2[3];
                mma_f16(acc[np * 2    ], af, bf[0]);
                mma_f16(acc[np * 2 + 1], af, bf[1]);
            }
        }

        __syncthreads();
        if (tt + 2 < KVC / 64) stage(tt + 2, buf);
        else asm volatile("cp.async.commit_group;");
    }

    float* kvp = g_kv + bh * (HD * HD);
    #pragma unroll
    for (int nt = 0; nt < 8; nt++) {
        #pragma unroll
        for (int half_i = 0; half_i < 2; half_i++) {
            const int d = 16 * warp + g + half_i * 8;
            const int e = nt * 8 + tg * 2;
            atomicAdd(&kvp[d * HD + e    ], acc[nt][half_i * 2 + 0]);
            atomicAdd(&kvp[d * HD + e + 1], acc[nt][half_i * 2 + 1]);
        }
    }
    ksacc += __shfl_xor_sync(0xffffffffu, ksacc, 1);
    if ((tid & 1) == 0) atomicAdd(&g_ksum[bh * HD + d_sum], ksacc);
}

// ---------------- attn via tensor cores: o = (Q @ KV) * z ----------------
__global__ __launch_bounds__(128) void attn_kernel()
{
    const int bh = blockIdx.y;
    const int b  = bh / NH, h = bh % NH;
    const int nbase = blockIdx.x * 64;

    __shared__ __half qs [64][KT_STRIDE];
    __shared__ __half kvh[64][KT_STRIDE];
    __shared__ float kss[64];
    __shared__ float zs[64];

    const int tid  = threadIdx.x;
    const int lane = tid & 31;
    const int warp = tid >> 5;
    const int g  = lane >> 2;
    const int tg = lane & 3;
    const int lm_r = ((lane >> 3) & 1) * 8 + (lane & 7);
    const int lm_c = (lane >> 4) * 8;

    {
        const __half* base = g_qkv + (size_t)(b * SEQ + nbase) * QKVN + h * HD;
        #pragma unroll
        for (int i = 0; i < 4; i++) {
            const int idx = tid + i * 128;
            const int r = idx >> 3, c = (idx & 7) * 8;
            cp16h(&qs[r][c], base + (size_t)r * QKVN + c);
        }
        asm volatile("cp.async.commit_group;");
    }
    {
        const float2* kvp = (const float2*)(g_kv + bh * (HD * HD));
        #pragma unroll
        for (int i = 0; i < 16; i++) {
            const int idx = tid + i * 128;
            const int r = idx >> 5, c = (idx & 31) * 2;
            float2 v = kvp[idx];
            *(__half2*)&kvh[r][c] = __floats2half2_rn(v.x, v.y);
        }
    }
    if (tid < 64) kss[tid] = g_ksum[bh * HD + tid];
    asm volatile("cp.async.wait_group 0;");
    __syncthreads();

    {
        const int row = tid >> 1;
        const int d0 = (tid & 1) * 32;
        float dot = 0.f;
        #pragma unroll 8
        for (int j = 0; j < 32; j++)
            dot += __half2float(qs[row][d0 + j]) * kss[d0 + j];
        dot += __shfl_xor_sync(0xffffffffu, dot, 1);
        if ((tid & 1) == 0) zs[row] = 1.f / (dot + 1e-6f);
    }
    __syncthreads();

    float acc[8][4] = {};
    #pragma unroll
    for (int kstep = 0; kstep < 4; kstep++) {
        const int k0 = kstep * 16;
        uint32_t af[4];
        ldsm_x4(af, &qs[16 * warp + lm_r][k0 + lm_c]);
        #pragma unroll
        for (int np = 0; np < 4; np++) {
            uint32_t r2[4];
            uint32_t bf0[2], bf1[2];
            ldsm_x4_t(r2, &kvh[k0 + lm_r][np * 16 + lm_c]);
            bf0[0] = r2[0]; bf0[1] = r2[1];
            bf1[0] = r2[2]; bf1[1] = r2[3];
            mma_f16(acc[np * 2    ], af, bf0);
            mma_f16(acc[np * 2 + 1], af, bf1);
        }
    }

    #pragma unroll
    for (int half_i = 0; half_i < 2; half_i++) {
        const int row = 16 * warp + g + half_i * 8;
        const float z = zs[row];
        __half* op = g_attn + (size_t)(b * SEQ + nbase + row) * DIM + h * HD;
        #pragma unroll
        for (int nt = 0; nt < 8; nt++) {
            const int e = nt * 8 + tg * 2;
            *(__half2*)(op + e) = __floats2half2_rn(acc[nt][half_i * 2 + 0] * z,
                                                    acc[nt][half_i * 2 + 1] * z);
        }
    }
}

// ---------------- launch ----------------
extern "C" void kernel_launch(void* const* d_in, const int* in_sizes, int n_in,
                              void* d_out, int out_size)
{
    const float* x      = (const float*)d_in[0];
    const float* n1g    = (const float*)d_in[1];
    const float* n1b    = (const float*)d_in[2];
    const float* qkv_w  = (const float*)d_in[3];
    const float* qkv_b  = (const float*)d_in[4];
    const float* proj_w = (const float*)d_in[5];
    const float* proj_b = (const float*)d_in[6];
    const float* n2g    = (const float*)d_in[7];
    const float* n2b    = (const float*)d_in[8];
    const float* fc1_w  = (const float*)d_in[9];
    const float* fc1_b  = (const float*)d_in[10];
    const float* fc2_w  = (const float*)d_in[11];
    const float* fc2_b  = (const float*)d_in[12];
    float* out = (float*)d_out;

    void *p_ln, *p_qkv, *p_attn, *p_x1, *p_mlp, *p_wq, *p_wp, *p_w1, *p_w2;
    cudaGetSymbolAddress(&p_ln,   g_ln);
    cudaGetSymbolAddress(&p_qkv,  g_qkv);
    cudaGetSymbolAddress(&p_attn, g_attn);
    cudaGetSymbolAddress(&p_x1,   g_x1);
    cudaGetSymbolAddress(&p_mlp,  g_mlp);
    cudaGetSymbolAddress(&p_wq,   g_wq);
    cudaGetSymbolAddress(&p_wp,   g_wp);
    cudaGetSymbolAddress(&p_w1,   g_w1);
    cudaGetSymbolAddress(&p_w2,   g_w2);
    __half* ln   = (__half*)p_ln;
    __half* qkv  = (__half*)p_qkv;
    __half* attn = (__half*)p_attn;
    __half* x1   = (__half*)p_x1;
    __half* mlp  = (__half*)p_mlp;
    __half* wq   = (__half*)p_wq;
    __half* wp   = (__half*)p_wp;
    __half* w1   = (__half*)p_w1;
    __half* w2   = (__half*)p_w2;

    cudaFuncSetAttribute(gemm_f16<0>, cudaFuncAttributeMaxDynamicSharedMemorySize, GEMM_SMEM_BYTES);
    cudaFuncSetAttribute(gemm_f16<1>, cudaFuncAttributeMaxDynamicSharedMemorySize, GEMM_SMEM_BYTES);
    cudaFuncSetAttribute(gemm_f16<2>, cudaFuncAttributeMaxDynamicSharedMemorySize, GEMM_SMEM_BYTES);
    cudaFuncSetAttribute(gemm_f16<3>, cudaFuncAttributeMaxDynamicSharedMemorySize, GEMM_SMEM_BYTES);

    // 0. convert weights + zero kv state (single launch)
    cvt_all_w_kernel<<<(CVT_TOTAL4 + 255) / 256, 256>>>(qkv_w, proj_w, fc1_w, fc2_w);

    // 1. LN1 (fp32 in, fp16 out)
    ln_kernel<float><<<M_TOK / 8, 256>>>(x, n1g, n1b, ln);
    // 2. qkv GEMM + bias + phi on q,k (fp16 out)
    gemm_f16<0><<<dim3(QKVN / BN, M_TOK / BM), 256, GEMM_SMEM_BYTES>>>(ln, wq, qkv_b, nullptr, qkv, QKVN, DIM);
    // 3. kv = K^T V (tensor cores) + ksum per (b,h)
    kv_kernel<<<dim3(SEQ / KVC, BH), 128>>>();
    // 4. attn = (q @ kv) * z (tensor cores, fp16 out)
    attn_kernel<<<dim3(SEQ / 64, BH), 128>>>();
    // 5. proj GEMM + bias + residual(x fp32) -> x1 (fp16)
    gemm_f16<1><<<dim3(DIM / BN, M_TOK / BM), 256, GEMM_SMEM_BYTES>>>(attn, wp, proj_b, x, x1, DIM, DIM);
    // 6. LN2 (fp16 in, fp16 out)
    ln_kernel<__half><<<M_TOK / 8, 256>>>(x1, n2g, n2b, ln);
    // 7. fc1 GEMM + bias + gelu (fp16 out)
    gemm_f16<2><<<dim3(HID / BN, M_TOK / BM), 256, GEMM_SMEM_BYTES>>>(ln, w1, fc1_b, nullptr, mlp, HID, DIM);
    // 8. fc2 GEMM + bias + residual(x1 fp16) -> out (fp32)
    gemm_f16<3><<<dim3(DIM / BN, M_TOK / BM), 256, GEMM_SMEM_BYTES>>>(mlp, w2, fc2_b, x1, out, DIM, HID);
}

// round 16
// speedup vs baseline: 1.1898x; 1.0123x over previous
#include <cuda_runtime.h>
#include <cuda_fp16.h>
#include <math.h>
#include <stdint.h>

// ---------------- problem constants ----------------
#define M_TOK 32768          // 8 * 4096 tokens
#define SEQ   4096
#define DIM   384
#define NH    6
#define HD    64
#define BH    48             // batch*heads
#define QKVN  1152
#define HID   1536

// ---------------- scratch (static device arrays; no allocation) ----------------
__device__ __half g_ln  [(size_t)M_TOK * DIM];
__device__ __half g_qkv [(size_t)M_TOK * QKVN];
__device__ __half g_attn[(size_t)M_TOK * DIM];
__device__ __half g_x1  [(size_t)M_TOK * DIM];       // residual stream after attn (fp16)
__device__ __half g_mlp [(size_t)M_TOK * HID];
__device__ float  g_kv  [BH * HD * HD];
__device__ float  g_ksum[BH * HD];
__device__ __half g_wq [DIM * QKVN];
__device__ __half g_wp [DIM * DIM];
__device__ __half g_w1 [DIM * HID];
__device__ __half g_w2 [HID * DIM];

// ---------------- shared PTX helpers ----------------
__device__ __forceinline__ void cp16h(__half* dst, const __half* src) {
    uint32_t s = (uint32_t)__cvta_generic_to_shared(dst);
    asm volatile("cp.async.cg.shared.global [%0], [%1], 16;" :: "r"(s), "l"(src));
}
__device__ __forceinline__ void ldsm_x4(uint32_t* r, const __half* p) {
    uint32_t a = (uint32_t)__cvta_generic_to_shared(p);
    asm volatile("ldmatrix.sync.aligned.m8n8.x4.shared.b16 {%0,%1,%2,%3}, [%4];"
        : "=r"(r[0]), "=r"(r[1]), "=r"(r[2]), "=r"(r[3]) : "r"(a));
}
__device__ __forceinline__ void ldsm_x4_t(uint32_t* r, const __half* p) {
    uint32_t a = (uint32_t)__cvta_generic_to_shared(p);
    asm volatile("ldmatrix.sync.aligned.m8n8.x4.trans.shared.b16 {%0,%1,%2,%3}, [%4];"
        : "=r"(r[0]), "=r"(r[1]), "=r"(r[2]), "=r"(r[3]) : "r"(a));
}
__device__ __forceinline__ void mma_f16(float* d, const uint32_t* a, const uint32_t* b) {
    asm volatile(
        "mma.sync.aligned.m16n8k16.row.col.f32.f16.f16.f32 "
        "{%0,%1,%2,%3}, {%4,%5,%6,%7}, {%8,%9}, {%0,%1,%2,%3};"
        : "+f"(d[0]), "+f"(d[1]), "+f"(d[2]), "+f"(d[3])
        : "r"(a[0]), "r"(a[1]), "r"(a[2]), "r"(a[3]), "r"(b[0]), "r"(b[1]));
}
__device__ __forceinline__ float fast_gelu(float v) {
    const float two_u = 1.5957691216057308f * (v + 0.044715f * v * v * v);
    return v * (1.f / (1.f + __expf(-two_u)));
}
__device__ __forceinline__ float4 load4f(const float* p, int idx) {
    return ((const float4*)p)[idx];
}
__device__ __forceinline__ float4 load4f(const __half* p, int idx) {
    const __half2* h = (const __half2*)p + idx * 2;
    float2 a = __half22float2(h[0]), b = __half22float2(h[1]);
    return make_float4(a.x, a.y, b.x, b.y);
}

// ---------------- convert weights to fp16 + zero kv state, one launch ----------------
#define CVT_TOTAL4 442368
#define KV_ZERO4   ((BH * HD * HD) / 4)     // 36864
#define KSUM_ZERO4 ((BH * HD) / 4)          // 768
__global__ __launch_bounds__(256) void cvt_all_w_kernel(
    const float* __restrict__ qkv_w, const float* __restrict__ proj_w,
    const float* __restrict__ fc1_w, const float* __restrict__ fc2_w)
{
    const int i = blockIdx.x * 256 + threadIdx.x;
    if (i < KV_ZERO4)   ((float4*)g_kv)[i]   = make_float4(0.f, 0.f, 0.f, 0.f);
    if (i < KSUM_ZERO4) ((float4*)g_ksum)[i] = make_float4(0.f, 0.f, 0.f, 0.f);
    if (i >= CVT_TOTAL4) return;
    const float* src;
    __half* dst;
    int off;
    if (i < 110592)      { src = qkv_w;  dst = g_wq; off = i; }
    else if (i < 147456) { src = proj_w; dst = g_wp; off = i - 110592; }
    else if (i < 294912) { src = fc1_w;  dst = g_w1; off = i - 147456; }
    else                 { src = fc2_w;  dst = g_w2; off = i - 294912; }
    float4 v = ((const float4*)src)[off];
    __half2* d = (__half2*)(dst + (size_t)off * 4);
    d[0] = __floats2half2_rn(v.x, v.y);
    d[1] = __floats2half2_rn(v.z, v.w);
}

// ---------------- LayerNorm: warp per row, fp16 output, templated input ----------------
template<typename TIN>
__global__ __launch_bounds__(256) void ln_kernel(
    const TIN* __restrict__ x, const float* __restrict__ gma,
    const float* __restrict__ bta, __half* __restrict__ out)
{
    const int warp = threadIdx.x >> 5;
    const int lane = threadIdx.x & 31;
    const int row  = blockIdx.x * 8 + warp;
    const TIN* xr = x + (size_t)row * DIM;
    const float4* g4 = (const float4*)gma;
    const float4* b4 = (const float4*)bta;

    float4 v[3];
    #pragma unroll
    for (int i = 0; i < 3; i++) v[i] = load4f(xr, lane + i * 32);

    float s = 0.f, sq = 0.f;
    #pragma unroll
    for (int i = 0; i < 3; i++) {
        s  += v[i].x + v[i].y + v[i].z + v[i].w;
        sq += v[i].x*v[i].x + v[i].y*v[i].y + v[i].z*v[i].z + v[i].w*v[i].w;
    }
    #pragma unroll
    for (int o = 16; o > 0; o >>= 1) {
        s  += __shfl_xor_sync(0xffffffffu, s,  o);
        sq += __shfl_xor_sync(0xffffffffu, sq, o);
    }
    const float mean = s * (1.f / DIM);
    const float inv  = rsqrtf(sq * (1.f / DIM) - mean * mean + 1e-5f);

    #pragma unroll
    for (int i = 0; i < 3; i++) {
        const float4 gg = g4[lane + i * 32];
        const float4 bb = b4[lane + i * 32];
        __half2* d = (__half2*)(out + (size_t)row * DIM + (lane + i * 32) * 4);
        d[0] = __floats2half2_rn((v[i].x - mean) * inv * gg.x + bb.x,
                                 (v[i].y - mean) * inv * gg.y + bb.y);
        d[1] = __floats2half2_rn((v[i].z - mean) * inv * gg.z + bb.z,
                                 (v[i].w - mean) * inv * gg.w + bb.w);
    }
}

// ---------------- fp16 tensor-core GEMM, cp.async 3-stage, BK=64 ----------------
//   MODE 0: qkv  -> phi on cols<768, fp16 out
//   MODE 1: proj -> +res (fp32 x), fp16 out (x1)
//   MODE 2: fc1  -> gelu, fp16 out
//   MODE 3: fc2  -> +res (fp16 x1), fp32 out
#define BM 128
#define BN 128
#define BK 64
#define STAGES 3
#define AS_STRIDE 72                    // halfs; 144B row stride (144%128=16: conflict-free ldsm)
#define BS_STRIDE 136                   // halfs; 272B row stride (conflict-free ldsm.trans)
#define AS_BUF (BM * AS_STRIDE)         // 9216 halfs
#define BS_BUF (BK * BS_STRIDE)         // 8704 halfs
#define GEMM_SMEM_BYTES (STAGES * (AS_BUF + BS_BUF) * 2)   // 107520

template<int MODE>
__global__ __launch_bounds__(256, 2) void gemm_f16(
    const __half* __restrict__ A, const __half* __restrict__ W,
    const float* __restrict__ bias, const void* __restrict__ res,
    void* __restrict__ Cout, int N, int K)
{
    extern __shared__ __align__(16) __half smem_h[];
    __half* As = smem_h;
    __half* Bs = smem_h + STAGES * AS_BUF;

    const int tid  = threadIdx.x;
    const int lane = tid & 31;
    const int warp = tid >> 5;
    const int wm = warp >> 2;
    const int wn = warp & 3;
    const int g  = lane >> 2;
    const int tg = lane & 3;

    const int lm_r = ((lane >> 3) & 1) * 8 + (lane & 7);
    const int lm_c = (lane >> 4) * 8;

    const int bm = blockIdx.y * BM;
    const int bn = blockIdx.x * BN;
    const int T  = K / BK;

    auto stage = [&](int t) {
        const int s  = t % STAGES;
        const int kt = t * BK;
        __half* Ad = As + s * AS_BUF;
        __half* Bd = Bs + s * BS_BUF;
        #pragma unroll
        for (int i = 0; i < 4; i++) {              // A: 128x64 half = 1024 chunks of 8
            const int idx = tid + i * 256;
            const int m = idx >> 3, c = (idx & 7) * 8;
            cp16h(&Ad[m * AS_STRIDE + c], A + (size_t)(bm + m) * K + kt + c);
        }
        #pragma unroll
        for (int i = 0; i < 4; i++) {              // B: 64x128 half = 1024 chunks of 8
            const int idx = tid + i * 256;
            const int k = idx >> 4, c = (idx & 15) * 8;
            cp16h(&Bd[k * BS_STRIDE + c], W + (size_t)(kt + k) * N + bn + c);
        }
        asm volatile("cp.async.commit_group;");
    };

    stage(0);
    stage(1);

    float acc[4][4][4] = {};
    const int m_base = wm * 64;
    const int n_base = wn * 32;

    int buf = 0;
    for (int t = 0; t < T; t++) {
        asm volatile("cp.async.wait_group 1;");
        __syncthreads();

        const __half* Ab = As + buf * AS_BUF;
        const __half* Bb = Bs + buf * BS_BUF;

        #pragma unroll
        for (int ks = 0; ks < 4; ks++) {
            const int k0 = ks * 16;
            uint32_t af[4][4], bf[4][2];
            #pragma unroll
            for (int mt = 0; mt < 4; mt++)
                ldsm_x4(af[mt], Ab + (m_base + mt * 16 + lm_r) * AS_STRIDE + k0 + lm_c);
            #pragma unroll
            for (int np = 0; np < 2; np++) {
                uint32_t r[4];
                ldsm_x4_t(r, Bb + (k0 + lm_r) * BS_STRIDE + n_base + np * 16 + lm_c);
                bf[np * 2    ][0] = r[0]; bf[np * 2    ][1] = r[1];
                bf[np * 2 + 1][0] = r[2]; bf[np * 2 + 1][1] = r[3];
            }
            #pragma unroll
            for (int mt = 0; mt < 4; mt++)
                #pragma unroll
                for (int nt = 0; nt < 4; nt++)
                    mma_f16(acc[mt][nt], af[mt], bf[nt]);
        }

        if (t + 2 < T) stage(t + 2);
        else asm volatile("cp.async.commit_group;");

        buf = (buf + 1 == STAGES) ? 0 : buf + 1;
    }

    float*  Cf = (float*)Cout;
    __half* Ch = (__half*)Cout;
    const float*  resf = (const float*)res;
    const __half* resh = (const __half*)res;
    #pragma unroll
    for (int mt = 0; mt < 4; mt++) {
        #pragma unroll
        for (int half_i = 0; half_i < 2; half_i++) {
            const int row = bm + m_base + mt * 16 + g + half_i * 8;
            #pragma unroll
            for (int nt = 0; nt < 4; nt++) {
                const int col = bn + n_base + nt * 8 + tg * 2;
                float v0 = acc[mt][nt][half_i * 2 + 0] + bias[col];
                float v1 = acc[mt][nt][half_i * 2 + 1] + bias[col + 1];
                if (MODE == 0) {
                    if (col     < 768) v0 = (v0 > 0.f) ? (v0 + 1.f) : __expf(v0);
                    if (col + 1 < 768) v1 = (v1 > 0.f) ? (v1 + 1.f) : __expf(v1);
                    *(__half2*)(Ch + (size_t)row * N + col) = __floats2half2_rn(v0, v1);
                }
                if (MODE == 1) {
                    const float2 r = *(const float2*)(resf + (size_t)row * N + col);
                    v0 += r.x; v1 += r.y;
                    *(__half2*)(Ch + (size_t)row * N + col) = __floats2half2_rn(v0, v1);
                }
                if (MODE == 2) {
                    v0 = fast_gelu(v0);
                    v1 = fast_gelu(v1);
                    *(__half2*)(Ch + (size_t)row * N + col) = __floats2half2_rn(v0, v1);
                }
                if (MODE == 3) {
                    const float2 r = __half22float2(*(const __half2*)(resh + (size_t)row * N + col));
                    v0 += r.x; v1 += r.y;
                    *(float2*)(Cf + (size_t)row * N + col) = make_float2(v0, v1);
                }
            }
        }
    }
}

// ---------------- kv-state via tensor cores: kv = K^T V over 512-token chunks ----------------
#define KVC 512
#define KT_STRIDE 72
__global__ __launch_bounds__(128) void kv_kernel()
{
    const int bh = blockIdx.y;
    const int b  = bh / NH, h = bh % NH;
    const int nbase = blockIdx.x * KVC;

    __shared__ __half ks[2][64][KT_STRIDE];
    __shared__ __half vs[2][64][KT_STRIDE];

    const int tid  = threadIdx.x;
    const int lane = tid & 31;
    const int warp = tid >> 5;
    const int g  = lane >> 2;
    const int tg = lane & 3;
    const int lm_r = ((lane >> 3) & 1) * 8 + (lane & 7);
    const int lm_c = (lane >> 4) * 8;

    auto stage = [&](int tt, int buf) {
        const __half* base = g_qkv + (size_t)(b * SEQ + nbase + tt * 64) * QKVN + h * HD;
        #pragma unroll
        for (int i = 0; i < 4; i++) {
            const int idx = tid + i * 128;
            const int r = idx >> 3, c = (idx & 7) * 8;
            cp16h(&ks[buf][r][c], base + (size_t)r * QKVN + 384 + c);
            cp16h(&vs[buf][r][c], base + (size_t)r * QKVN + 768 + c);
        }
        asm volatile("cp.async.commit_group;");
    };

    stage(0, 0);
    stage(1, 1);

    float acc[8][4] = {};
    float ksacc = 0.f;
    const int d_sum  = tid >> 1;
    const int r_half = (tid & 1) * 32;

    for (int tt = 0; tt < KVC / 64; tt++) {
        asm volatile("cp.async.wait_group 1;");
        __syncthreads();
        const int buf = tt & 1;

        #pragma unroll 8
        for (int r = 0; r < 32; r++)
            ksacc += __half2float(ks[buf][r_half + r][d_sum]);

        #pragma unroll
        for (int kstep = 0; kstep < 4; kstep++) {
            const int t0 = kstep * 16;
            uint32_t rr[4], af[4], bf[4][2];
            ldsm_x4_t(rr, &ks[buf][t0 + lm_r][16 * warp + lm_c]);
            af[0] = rr[0]; af[1] = rr[2]; af[2] = rr[1]; af[3] = rr[3];
            #pragma unroll
            for (int np = 0; np < 4; np++) {
                uint32_t r2[4];
                ldsm_x4_t(r2, &vs[buf][t0 + lm_r][np * 16 + lm_c]);
                bf[0][0] = r2[0]; bf[0][1] = r2[1];
                bf[1][0] = r2[2]; bf[1][1] = r2[3];
                mma_f16(acc[np * 2    ], af, bf[0]);
                mma_f16(acc[np * 2 + 1], af, bf[1]);
            }
        }

        __syncthreads();
        if (tt + 2 < KVC / 64) stage(tt + 2, buf);
        else asm volatile("cp.async.commit_group;");
    }

    float* kvp = g_kv + bh * (HD * HD);
    #pragma unroll
    for (int nt = 0; nt < 8; nt++) {
        #pragma unroll
        for (int half_i = 0; half_i < 2; half_i++) {
            const int d = 16 * warp + g + half_i * 8;
            const int e = nt * 8 + tg * 2;
            atomicAdd(&kvp[d * HD + e    ], acc[nt][half_i * 2 + 0]);
            atomicAdd(&kvp[d * HD + e + 1], acc[nt][half_i * 2 + 1]);
        }
    }
    ksacc += __shfl_xor_sync(0xffffffffu, ksacc, 1);
    if ((tid & 1) == 0) atomicAdd(&g_ksum[bh * HD + d_sum], ksacc);
}

// ---------------- attn via tensor cores: o = (Q @ KV) * z ----------------
__global__ __launch_bounds__(128) void attn_kernel()
{
    const int bh = blockIdx.y;
    const int b  = bh / NH, h = bh % NH;
    const int nbase = blockIdx.x * 64;

    __shared__ __half qs [64][KT_STRIDE];
    __shared__ __half kvh[64][KT_STRIDE];
    __shared__ float kss[64];
    __shared__ float zs[64];

    const int tid  = threadIdx.x;
    const int lane = tid & 31;
    const int warp = tid >> 5;
    const int g  = lane >> 2;
    const int tg = lane & 3;
    const int lm_r = ((lane >> 3) & 1) * 8 + (lane & 7);
    const int lm_c = (lane >> 4) * 8;

    {
        const __half* base = g_qkv + (size_t)(b * SEQ + nbase) * QKVN + h * HD;
        #pragma unroll
        for (int i = 0; i < 4; i++) {
            const int idx = tid + i * 128;
            const int r = idx >> 3, c = (idx & 7) * 8;
            cp16h(&qs[r][c], base + (size_t)r * QKVN + c);
        }
        asm volatile("cp.async.commit_group;");
    }
    {
        const float2* kvp = (const float2*)(g_kv + bh * (HD * HD));
        #pragma unroll
        for (int i = 0; i < 16; i++) {
            const int idx = tid + i * 128;
            const int r = idx >> 5, c = (idx & 31) * 2;
            float2 v = kvp[idx];
            *(__half2*)&kvh[r][c] = __floats2half2_rn(v.x, v.y);
        }
    }
    if (tid < 64) kss[tid] = g_ksum[bh * HD + tid];
    asm volatile("cp.async.wait_group 0;");
    __syncthreads();

    {
        const int row = tid >> 1;
        const int d0 = (tid & 1) * 32;
        float dot = 0.f;
        #pragma unroll 8
        for (int j = 0; j < 32; j++)
            dot += __half2float(qs[row][d0 + j]) * kss[d0 + j];
        dot += __shfl_xor_sync(0xffffffffu, dot, 1);
        if ((tid & 1) == 0) zs[row] = 1.f / (dot + 1e-6f);
    }
    __syncthreads();

    float acc[8][4] = {};
    #pragma unroll
    for (int kstep = 0; kstep < 4; kstep++) {
        const int k0 = kstep * 16;
        uint32_t af[4];
        ldsm_x4(af, &qs[16 * warp + lm_r][k0 + lm_c]);
        #pragma unroll
        for (int np = 0; np < 4; np++) {
            uint32_t r2[4];
            uint32_t bf0[2], bf1[2];
            ldsm_x4_t(r2, &kvh[k0 + lm_r][np * 16 + lm_c]);
            bf0[0] = r2[0]; bf0[1] = r2[1];
            bf1[0] = r2[2]; bf1[1] = r2[3];
            mma_f16(acc[np * 2    ], af, bf0);
            mma_f16(acc[np * 2 + 1], af, bf1);
        }
    }

    #pragma unroll
    for (int half_i = 0; half_i < 2; half_i++) {
        const int row = 16 * warp + g + half_i * 8;
        const float z = zs[row];
        __half* op = g_attn + (size_t)(b * SEQ + nbase + row) * DIM + h * HD;
        #pragma unroll
        for (int nt = 0; nt < 8; nt++) {
            const int e = nt * 8 + tg * 2;
            *(__half2*)(op + e) = __floats2half2_rn(acc[nt][half_i * 2 + 0] * z,
                                                    acc[nt][half_i * 2 + 1] * z);
        }
    }
}

// ---------------- launch ----------------
extern "C" void kernel_launch(void* const* d_in, const int* in_sizes, int n_in,
                              void* d_out, int out_size)
{
    const float* x      = (const float*)d_in[0];
    const float* n1g    = (const float*)d_in[1];
    const float* n1b    = (const float*)d_in[2];
    const float* qkv_w  = (const float*)d_in[3];
    const float* qkv_b  = (const float*)d_in[4];
    const float* proj_w = (const float*)d_in[5];
    const float* proj_b = (const float*)d_in[6];
    const float* n2g    = (const float*)d_in[7];
    const float* n2b    = (const float*)d_in[8];
    const float* fc1_w  = (const float*)d_in[9];
    const float* fc1_b  = (const float*)d_in[10];
    const float* fc2_w  = (const float*)d_in[11];
    const float* fc2_b  = (const float*)d_in[12];
    float* out = (float*)d_out;

    void *p_ln, *p_qkv, *p_attn, *p_x1, *p_mlp, *p_wq, *p_wp, *p_w1, *p_w2;
    cudaGetSymbolAddress(&p_ln,   g_ln);
    cudaGetSymbolAddress(&p_qkv,  g_qkv);
    cudaGetSymbolAddress(&p_attn, g_attn);
    cudaGetSymbolAddress(&p_x1,   g_x1);
    cudaGetSymbolAddress(&p_mlp,  g_mlp);
    cudaGetSymbolAddress(&p_wq,   g_wq);
    cudaGetSymbolAddress(&p_wp,   g_wp);
    cudaGetSymbolAddress(&p_w1,   g_w1);
    cudaGetSymbolAddress(&p_w2,   g_w2);
    __half* ln   = (__half*)p_ln;
    __half* qkv  = (__half*)p_qkv;
    __half* attn = (__half*)p_attn;
    __half* x1   = (__half*)p_x1;
    __half* mlp  = (__half*)p_mlp;
    __half* wq   = (__half*)p_wq;
    __half* wp   = (__half*)p_wp;
    __half* w1   = (__half*)p_w1;
    __half* w2   = (__half*)p_w2;

    cudaFuncSetAttribute(gemm_f16<0>, cudaFuncAttributeMaxDynamicSharedMemorySize, GEMM_SMEM_BYTES);
    cudaFuncSetAttribute(gemm_f16<1>, cudaFuncAttributeMaxDynamicSharedMemorySize, GEMM_SMEM_BYTES);
    cudaFuncSetAttribute(gemm_f16<2>, cudaFuncAttributeMaxDynamicSharedMemorySize, GEMM_SMEM_BYTES);
    cudaFuncSetAttribute(gemm_f16<3>, cudaFuncAttributeMaxDynamicSharedMemorySize, GEMM_SMEM_BYTES);

    // 0. convert weights + zero kv state (single launch)
    cvt_all_w_kernel<<<(CVT_TOTAL4 + 255) / 256, 256>>>(qkv_w, proj_w, fc1_w, fc2_w);

    // 1. LN1 (fp32 in, fp16 out)
    ln_kernel<float><<<M_TOK / 8, 256>>>(x, n1g, n1b, ln);
    // 2. qkv GEMM + bias + phi on q,k (fp16 out)
    gemm_f16<0><<<dim3(QKVN / BN, M_TOK / BM), 256, GEMM_SMEM_BYTES>>>(ln, wq, qkv_b, nullptr, qkv, QKVN, DIM);
    // 3. kv = K^T V (tensor cores) + ksum per (b,h)
    kv_kernel<<<dim3(SEQ / KVC, BH), 128>>>();
    // 4. attn = (q @ kv) * z (tensor cores, fp16 out)
    attn_kernel<<<dim3(SEQ / 64, BH), 128>>>();
    // 5. proj GEMM + bias + residual(x fp32) -> x1 (fp16)
    gemm_f16<1><<<dim3(DIM / BN, M_TOK / BM), 256, GEMM_SMEM_BYTES>>>(attn, wp, proj_b, x, x1, DIM, DIM);
    // 6. LN2 (fp16 in, fp16 out)
    ln_kernel<__half><<<M_TOK / 8, 256>>>(x1, n2g, n2b, ln);
    // 7. fc1 GEMM + bias + gelu (fp16 out)
    gemm_f16<2><<<dim3(HID / BN, M_TOK / BM), 256, GEMM_SMEM_BYTES>>>(ln, w1, fc1_b, nullptr, mlp, HID, DIM);
    // 8. fc2 GEMM + bias + residual(x1 fp16) -> out (fp32)
    gemm_f16<3><<<dim3(DIM / BN, M_TOK / BM), 256, GEMM_SMEM_BYTES>>>(mlp, w2, fc2_b, x1, out, DIM, HID);
}